// round 10
// baseline (speedup 1.0000x reference)
#include <cuda_runtime.h>
#include <cstdint>
#include <cmath>

#define kT   2048
#define kE   768
#define kH   12
#define kD   64
#define kWIN 128
#define kPVSPLIT 4
#define kTB  (kT / 128)                 // 16 row/col tiles in sim
#define kTRI (kTB * (kTB + 1) / 2)      // 136 lower-triangle tiles

// ---------------- device scratch (no allocations allowed) ----------------
__device__ float g_h[kT * kE];                 // rmsnorm output
__device__ float g_q[kT * kE];                 // normalized q projection
__device__ float g_v[kT * kE];                 // value proj
__device__ float g_pvpart[kPVSPLIT * kT * kE]; // k-split partials for PV
__device__ float g_c[8];                       // derived scalars
__device__ float g_ktab[kT];                   // exp(-d/8) table
__device__ float g_scratch[50331648];          // H*T*T raw-score scratch (only if attn not an output)

// ---------------- constants / emotion statistics ----------------
// bias[i,j] = e[i]*exp(-|i-j|/8).  mean = sum_i e_i*S1_i / T^2,
// sumsq = sum_i e_i^2*S2_i, with S1,S2 closed-form geometric sums.
__global__ void consts_kernel(const float* __restrict__ emo, const float* sig,
                              const float* bl, const float* bg)
{
    __shared__ float s1[1024], s2[1024];
    const int tid = threadIdx.x;
    const float r1 = expf(-0.125f);
    const float r2 = expf(-0.25f);
    float a1 = 0.f, a2 = 0.f;
    for (int i = tid; i < kT; i += 1024) {
        float l1  = (r1 - expf(-0.125f * (float)(i + 1))) / (1.f - r1);
        float rr1 = (r1 - expf(-0.125f * (float)(kT - i))) / (1.f - r1);
        float S1 = 1.f + l1 + rr1;
        float l2  = (r2 - expf(-0.25f * (float)(i + 1))) / (1.f - r2);
        float rr2 = (r2 - expf(-0.25f * (float)(kT - i))) / (1.f - r2);
        float S2 = 1.f + l2 + rr2;
        float e = emo[i];
        a1 += e * S1;
        a2 += e * e * S2;
        g_ktab[i] = expf(-0.125f * (float)i);
    }
    s1[tid] = a1; s2[tid] = a2; __syncthreads();
    for (int s = 512; s > 0; s >>= 1) {
        if (tid < s) { s1[tid] += s1[tid + s]; s2[tid] += s2[tid + s]; }
        __syncthreads();
    }
    if (tid == 0) {
        const float NN = (float)kT * (float)kT;
        float mean = s1[0] / NN;
        float var  = (s2[0] - NN * mean * mean) / (NN - 1.f);
        float sd   = fmaxf(sqrtf(fmaxf(var, 0.f)), 1e-6f);
        float sgm  = fmaxf(sig[0], 1e-4f);
        g_c[0] = 1.f / (sgm * sgm);
        float glv = 1.f / (1.f + expf(-bl[0]));
        float ggv = 1.f / (1.f + expf(-bg[0]));
        g_c[1] = logf(1e-4f);                   // neither
        g_c[2] = logf(fmaxf(ggv, 1e-4f));       // strided only
        g_c[3] = logf(fmaxf(glv, 1e-4f));       // local only
        g_c[4] = logf(fmaxf(glv + ggv, 1e-4f)); // both
        g_c[5] = mean;
        g_c[6] = 0.5f / sd;                     // GAM / std
    }
}

// ---------------- RMSNorm ----------------
__global__ void rmsnorm_kernel(const float* __restrict__ x, const float* __restrict__ w)
{
    const int row = blockIdx.x;
    const float* xr = x + (size_t)row * kE;
    __shared__ float red[256];
    float ss = 0.f;
    for (int k = threadIdx.x; k < kE; k += 256) { float v = xr[k]; ss += v * v; }
    red[threadIdx.x] = ss; __syncthreads();
    for (int s = 128; s > 0; s >>= 1) {
        if (threadIdx.x < s) red[threadIdx.x] += red[threadIdx.x + s];
        __syncthreads();
    }
    float scale = rsqrtf(red[0] / (float)kE + 1e-6f);
    for (int k = threadIdx.x; k < kE; k += 256)
        g_h[(size_t)row * kE + k] = xr[k] * scale * w[k];
}

// ---------------- generic C = A * B^T GEMM (128x128x16, 8x8 micro, dbl-buffered)
// B1 != nullptr : blockIdx.z selects (B0,C0) vs (B1,C1)   [dual-weight proj]
// B1 == nullptr : per-z offsets az/bz/cz                   [per-head sim, out-proj]
// nacc > 1      : A element = sum of nacc chunks at stride accstride
// sym != 0      : A==B symmetric; blockIdx.x is a LINEAR lower-triangle index
//                 (decoded to bi>=bj); result mirrored into the upper tile.
// norm64 != 0   : (dual-proj z==0 only) L2-normalize each 64-col group per row
//                 in the epilogue (fused F.normalize for q heads).
__global__ void __launch_bounds__(256, 2)
gemm_abt(const float* __restrict__ A, int nacc, size_t accstride,
         const float* __restrict__ B0, const float* __restrict__ B1,
         float* C0, float* C1,
         int lda, int ldb, int ldc, int K,
         size_t az, size_t bz, size_t cz, int sym, int norm64)
{
    const int z = blockIdx.z;
    int bi, bj;
    if (sym) {
        int l = blockIdx.x;                       // 0 .. kTRI-1
        bi = (int)((sqrtf(8.f * l + 1.f) - 1.f) * 0.5f);
        while (bi * (bi + 1) / 2 > l) bi--;       // exact correction
        while ((bi + 1) * (bi + 2) / 2 <= l) bi++;
        bj = l - bi * (bi + 1) / 2;               // bj <= bi
    } else {
        bi = blockIdx.y; bj = blockIdx.x;
    }
    const float* Ap = A + az * (size_t)z;
    const float* Bp; float* Cp;
    if (B1) { Bp = z ? B1 : B0; Cp = z ? C1 : C0; }
    else    { Bp = B0 + bz * (size_t)z; Cp = C0 + cz * (size_t)z; }
    const int bm = bi * 128, bn = bj * 128;

    __shared__ float As[16][132];
    __shared__ float Bs[16][132];
    const int tid = threadIdx.x;
    const int tx = tid & 15, ty = tid >> 4;
    const int sk = tid & 15;      // staging k (constant: 256 % 16 == 0)
    const int sm0 = tid >> 4;     // staging base m
    float acc[8][8] = {};
    float ra[8], rb[8];

    // preload tile 0
    #pragma unroll
    for (int i = 0; i < 8; i++) {
        int m = sm0 + i * 16;
        size_t ai = (size_t)(bm + m) * lda + sk;
        float av = Ap[ai];
        for (int c = 1; c < nacc; c++) av += Ap[ai + accstride * c];
        ra[i] = av;
        rb[i] = Bp[(size_t)(bn + m) * ldb + sk];
    }

    for (int k0 = 0; k0 < K; k0 += 16) {
        #pragma unroll
        for (int i = 0; i < 8; i++) {
            int m = sm0 + i * 16;
            As[sk][m] = ra[i];
            Bs[sk][m] = rb[i];
        }
        __syncthreads();
        if (k0 + 16 < K) {
            #pragma unroll
            for (int i = 0; i < 8; i++) {
                int m = sm0 + i * 16;
                size_t ai = (size_t)(bm + m) * lda + (k0 + 16 + sk);
                float av = Ap[ai];
                for (int c = 1; c < nacc; c++) av += Ap[ai + accstride * c];
                ra[i] = av;
                rb[i] = Bp[(size_t)(bn + m) * ldb + (k0 + 16 + sk)];
            }
        }
        #pragma unroll
        for (int k = 0; k < 16; k++) {
            float a[8], b[8];
            *(float4*)(a)     = *(const float4*)&As[k][ty * 8];
            *(float4*)(a + 4) = *(const float4*)&As[k][ty * 8 + 4];
            *(float4*)(b)     = *(const float4*)&Bs[k][tx * 8];
            *(float4*)(b + 4) = *(const float4*)&Bs[k][tx * 8 + 4];
            #pragma unroll
            for (int i2 = 0; i2 < 8; i2++)
                #pragma unroll
                for (int j2 = 0; j2 < 8; j2++)
                    acc[i2][j2] = fmaf(a[i2], b[j2], acc[i2][j2]);
        }
        __syncthreads();
    }
    // fused per-head L2 normalization (q projection only):
    // row bm+ty*8+i2; the 64 cols of one head live on the 8 threads sharing
    // ty with tx in {0..7} or {8..15}; tx = low 4 bits of lane id, so
    // shfl_xor 1/2/4 reduces exactly over that group.
    if (norm64 && B1 && z == 0) {
        #pragma unroll
        for (int i2 = 0; i2 < 8; i2++) {
            float ss = 0.f;
            #pragma unroll
            for (int j2 = 0; j2 < 8; j2++) ss += acc[i2][j2] * acc[i2][j2];
            #pragma unroll
            for (int s = 1; s < 8; s <<= 1) ss += __shfl_xor_sync(0xffffffffu, ss, s);
            float inv = rsqrtf(fmaxf(ss, 1e-24f));   // == 1/max(sqrt(ss),1e-12)
            #pragma unroll
            for (int j2 = 0; j2 < 8; j2++) acc[i2][j2] *= inv;
        }
    }
    #pragma unroll
    for (int i2 = 0; i2 < 8; i2++) {
        size_t r = (size_t)(bm + ty * 8 + i2) * ldc + bn + tx * 8;
        *(float4*)&Cp[r]     = *(float4*)&acc[i2][0];
        *(float4*)&Cp[r + 4] = *(float4*)&acc[i2][4];
    }
    if (sym && bj < bi) {  // mirror tile (identical fp values by commutativity)
        #pragma unroll
        for (int j2 = 0; j2 < 8; j2++) {
            float t[8];
            #pragma unroll
            for (int i2 = 0; i2 < 8; i2++) t[i2] = acc[i2][j2];
            size_t r = (size_t)(bn + tx * 8 + j2) * ldc + bm + ty * 8;
            *(float4*)&Cp[r]     = *(float4*)&t[0];
            *(float4*)&Cp[r + 4] = *(float4*)&t[4];
        }
    }
}

// ---------------- fused score-transform + softmax (row-wise, float4 I/O) ----
// 512 threads: each thread owns exactly one float4 of the 2048-wide row.
// Reductions: warp shuffle + 16 warp partials in smem (2 barriers per reduction).
__global__ void __launch_bounds__(512)
softmax_kernel(const float* __restrict__ emo, float* __restrict__ S)
{
    const int row = blockIdx.x;
    const int hd  = blockIdx.y;
    float* rp = S + ((size_t)hd * kT + row) * kT;
    float4* rp4 = (float4*)rp;
    __shared__ float kt[kT];
    __shared__ float wred[16];
    const int tid  = threadIdx.x;
    const int lane = tid & 31;
    const int wrp  = tid >> 5;
    for (int j = tid; j < kT; j += 512) kt[j] = g_ktab[j];
    const float c0 = g_c[0];
    const float gNone = g_c[1], gStr = g_c[2], gLoc = g_c[3], gBoth = g_c[4];
    const float mean = g_c[5], esc = g_c[6];
    const float ei = emo[row];
    __syncthreads();

    float4 sv = rp4[tid];
    float o[4] = {sv.x, sv.y, sv.z, sv.w};
    float m = -1e30f;
    #pragma unroll
    for (int u = 0; u < 4; u++) {
        int j = tid * 4 + u;
        float sim = fminf(fmaxf(o[u], -1.f), 1.f);
        float sc = -fmaxf(2.f - 2.f * sim, 0.f) * c0;
        sc = fminf(fmaxf(sc, -12.f), 12.f);
        int d = row > j ? row - j : j - row;
        float g;
        if (d <= kWIN) g = ((j & 7) == 0) ? gBoth : gLoc;
        else           g = ((j & 7) == 0) ? gStr  : gNone;
        sc += g;
        sc += (ei * kt[d] - mean) * esc;
        o[u] = sc;
        m = fmaxf(m, sc);
    }
    // block max: warp butterfly -> 16 partials -> warp 0 butterfly -> broadcast
    #pragma unroll
    for (int s = 16; s > 0; s >>= 1) m = fmaxf(m, __shfl_xor_sync(0xffffffffu, m, s));
    if (lane == 0) wred[wrp] = m;
    __syncthreads();
    {
        float t = (lane < 16) ? wred[lane] : -1e30f;
        #pragma unroll
        for (int s = 8; s > 0; s >>= 1) t = fmaxf(t, __shfl_xor_sync(0xffffffffu, t, s));
        if (tid == 0) wred[0] = t;
    }
    __syncthreads();
    m = wred[0];

    float sum = 0.f;
    #pragma unroll
    for (int u = 0; u < 4; u++) { o[u] = __expf(o[u] - m); sum += o[u]; }
    __syncthreads();  // protect wred reuse
    #pragma unroll
    for (int s = 16; s > 0; s >>= 1) sum += __shfl_xor_sync(0xffffffffu, sum, s);
    if (lane == 0) wred[wrp] = sum;
    __syncthreads();
    {
        float t = (lane < 16) ? wred[lane] : 0.f;
        #pragma unroll
        for (int s = 8; s > 0; s >>= 1) t += __shfl_xor_sync(0xffffffffu, t, s);
        if (tid == 0) wred[0] = t;
    }
    __syncthreads();
    float inv = 1.f / wred[0];
    rp4[tid] = make_float4(o[0] * inv, o[1] * inv, o[2] * inv, o[3] * inv);
}

// ---------------- PV: pvpart[chunk] = attn[:, kchunk] @ v[kchunk] ----------
// 256 threads, 128x64 tile, 8x4 microtile, k-tile 32, double-buffered, K-split 4.
__global__ void __launch_bounds__(256, 2)
pv_kernel(const float* __restrict__ S)
{
    const int hd    = blockIdx.z;
    const int chunk = blockIdx.y;             // 0..kPVSPLIT-1
    const int bm    = blockIdx.x * 128;
    const float* A = S + (size_t)hd * kT * kT;
    const float* B = g_v + hd * kD;

    __shared__ float As[32][132];
    __shared__ float Bs[32][68];
    const int tid = threadIdx.x;
    const int tx = tid & 15, ty = tid >> 4;   // col group (x4), row group (x8)
    const int ak = tid & 31;                  // staging: A k (constant)
    const int am0 = tid >> 5;                 // A base m (stride 8)
    const int bn_ = tid & 63;                 // staging: B n (constant)
    const int bk0 = tid >> 6;                 // B base k (stride 4)
    float acc[8][4] = {};
    float ra[16], rb[8];

    const int kb = chunk * (kT / kPVSPLIT), ke2 = kb + (kT / kPVSPLIT);

    // preload first k-tile
    #pragma unroll
    for (int i = 0; i < 16; i++)
        ra[i] = A[(size_t)(bm + am0 + i * 8) * kT + (kb + ak)];
    #pragma unroll
    for (int i = 0; i < 8; i++)
        rb[i] = B[(size_t)(kb + bk0 + i * 4) * kE + bn_];

    for (int k0 = kb; k0 < ke2; k0 += 32) {
        #pragma unroll
        for (int i = 0; i < 16; i++) As[ak][am0 + i * 8] = ra[i];
        #pragma unroll
        for (int i = 0; i < 8; i++)  Bs[bk0 + i * 4][bn_] = rb[i];
        __syncthreads();
        if (k0 + 32 < ke2) {
            #pragma unroll
            for (int i = 0; i < 16; i++)
                ra[i] = A[(size_t)(bm + am0 + i * 8) * kT + (k0 + 32 + ak)];
            #pragma unroll
            for (int i = 0; i < 8; i++)
                rb[i] = B[(size_t)(k0 + 32 + bk0 + i * 4) * kE + bn_];
        }
        #pragma unroll
        for (int k = 0; k < 32; k++) {
            float a[8], b[4];
            *(float4*)(a)     = *(const float4*)&As[k][ty * 8];
            *(float4*)(a + 4) = *(const float4*)&As[k][ty * 8 + 4];
            *(float4*)(b)     = *(const float4*)&Bs[k][tx * 4];
            #pragma unroll
            for (int i2 = 0; i2 < 8; i2++)
                #pragma unroll
                for (int j2 = 0; j2 < 4; j2++)
                    acc[i2][j2] = fmaf(a[i2], b[j2], acc[i2][j2]);
        }
        __syncthreads();
    }
    float* Cp = g_pvpart + (size_t)chunk * kT * kE;
    #pragma unroll
    for (int i2 = 0; i2 < 8; i2++) {
        size_t r = (size_t)(bm + ty * 8 + i2) * kE + hd * kD + tx * 4;
        *(float4*)&Cp[r] = *(float4*)&acc[i2][0];
    }
}

// ---------------- host launcher ----------------
extern "C" void kernel_launch(void* const* d_in, const int* in_sizes, int n_in,
                              void* d_out, int out_size)
{
    const float* x    = (const float*)d_in[0];
    const float* emo  = (const float*)d_in[1];
    const float* wqk  = (const float*)d_in[2];
    const float* wv   = (const float*)d_in[3];
    const float* wout = (const float*)d_in[4];
    const float* rmsw = (const float*)d_in[5];
    const float* sig  = (const float*)d_in[6];
    const float* bl   = (const float*)d_in[7];
    const float* bg   = (const float*)d_in[8];

    float* outbuf = (float*)d_out;
    const long long OUTN = (long long)kT * kE;          // 1,572,864
    const long long ATTN = (long long)kH * kT * kT;     // 50,331,648
    const long long osz  = (long long)out_size;
    float* out_o = nullptr;
    float* attn  = nullptr;
    if (osz >= OUTN + ATTN)  { out_o = outbuf; attn = outbuf + OUTN; }
    else if (osz == ATTN)    { attn = outbuf; }
    else                     { out_o = outbuf; }

    void *ph, *pq, *pv_, *ppv, *pscr;
    cudaGetSymbolAddress(&ph,  g_h);
    cudaGetSymbolAddress(&pq,  g_q);
    cudaGetSymbolAddress(&pv_, g_v);
    cudaGetSymbolAddress(&ppv, g_pvpart);
    cudaGetSymbolAddress(&pscr, g_scratch);
    float* h_   = (float*)ph;
    float* q_   = (float*)pq;
    float* v_   = (float*)pv_;
    float* pvp  = (float*)ppv;
    float* S    = attn ? attn : (float*)pscr;

    consts_kernel<<<1, 1024>>>(emo, sig, bl, bg);
    rmsnorm_kernel<<<kT, 256>>>(x, rmsw);
    // shared = h @ w_qk^T (L2-normalized per head in epilogue) ; values = h @ w_v^T
    gemm_abt<<<dim3(kE / 128, kT / 128, 2), 256>>>(h_, 1, 0, wqk, wv, q_, v_,
                                                   kE, kE, kE, kE, 0, 0, 0, 0, 1);
    // sim = q @ q^T per head (symmetric: lower-triangle linear grid, mirror-store)
    gemm_abt<<<dim3(kTRI, 1, kH), 256>>>(q_, 1, 0, q_, nullptr, S, nullptr,
                                         kE, kE, kT, kD,
                                         (size_t)kD, (size_t)kD,
                                         (size_t)kT * kT, 1, 0);
    softmax_kernel<<<dim3(kT, kH), 512>>>(emo, S);
    pv_kernel<<<dim3(kT / 128, kPVSPLIT, kH), 256>>>(S);
    if (out_o)  // out = (sum of kPVSPLIT partials) @ w_out^T (recombine fused into A-load)
        gemm_abt<<<dim3(kE / 128, kT / 128, 1), 256>>>(pvp, kPVSPLIT, (size_t)kT * kE,
                                                       wout, nullptr, out_o, nullptr,
                                                       kE, kE, kE, kE, 0, 0, 0, 0, 0);
}

// round 15
// speedup vs baseline: 1.6273x; 1.6273x over previous
#include <cuda_runtime.h>
#include <cuda_bf16.h>
#include <cstdint>
#include <cmath>

#define kT   2048
#define kE   768
#define kH   12
#define kD   64
#define kWIN 128
#define kPVSPLIT 2
#define kTB  (kT / 128)                 // 16 row/col tiles in sim
#define kTRI (kTB * (kTB + 1) / 2)      // 136 lower-triangle tiles

// ---------------- device scratch (no allocations allowed) ----------------
__device__ float g_h[kT * kE];                 // rmsnorm output
__device__ float g_q[kT * kE];                 // normalized q projection
__device__ float g_v[kT * kE];                 // value proj
__device__ float g_pvpart[kPVSPLIT * kT * kE]; // k-split partials for PV
__device__ float g_c[8];                       // derived scalars
__device__ float g_ktab[kT];                   // exp(-d/8) table
__device__ float g_scratch[50331648];          // H*T*T raw-score scratch (only if attn not an output)

// ---------------- constants / emotion statistics ----------------
__global__ void consts_kernel(const float* __restrict__ emo, const float* sig,
                              const float* bl, const float* bg)
{
    __shared__ float s1[1024], s2[1024];
    const int tid = threadIdx.x;
    const float r1 = expf(-0.125f);
    const float r2 = expf(-0.25f);
    float a1 = 0.f, a2 = 0.f;
    for (int i = tid; i < kT; i += 1024) {
        float l1  = (r1 - expf(-0.125f * (float)(i + 1))) / (1.f - r1);
        float rr1 = (r1 - expf(-0.125f * (float)(kT - i))) / (1.f - r1);
        float S1 = 1.f + l1 + rr1;
        float l2  = (r2 - expf(-0.25f * (float)(i + 1))) / (1.f - r2);
        float rr2 = (r2 - expf(-0.25f * (float)(kT - i))) / (1.f - r2);
        float S2 = 1.f + l2 + rr2;
        float e = emo[i];
        a1 += e * S1;
        a2 += e * e * S2;
        g_ktab[i] = expf(-0.125f * (float)i);
    }
    s1[tid] = a1; s2[tid] = a2; __syncthreads();
    for (int s = 512; s > 0; s >>= 1) {
        if (tid < s) { s1[tid] += s1[tid + s]; s2[tid] += s2[tid + s]; }
        __syncthreads();
    }
    if (tid == 0) {
        const float NN = (float)kT * (float)kT;
        float mean = s1[0] / NN;
        float var  = (s2[0] - NN * mean * mean) / (NN - 1.f);
        float sd   = fmaxf(sqrtf(fmaxf(var, 0.f)), 1e-6f);
        float sgm  = fmaxf(sig[0], 1e-4f);
        g_c[0] = 1.f / (sgm * sgm);
        float glv = 1.f / (1.f + expf(-bl[0]));
        float ggv = 1.f / (1.f + expf(-bg[0]));
        g_c[1] = logf(1e-4f);                   // neither
        g_c[2] = logf(fmaxf(ggv, 1e-4f));       // strided only
        g_c[3] = logf(fmaxf(glv, 1e-4f));       // local only
        g_c[4] = logf(fmaxf(glv + ggv, 1e-4f)); // both
        g_c[5] = mean;
        g_c[6] = 0.5f / sd;                     // GAM / std
    }
}

// ---------------- RMSNorm ----------------
__global__ void rmsnorm_kernel(const float* __restrict__ x, const float* __restrict__ w)
{
    const int row = blockIdx.x;
    const float* xr = x + (size_t)row * kE;
    __shared__ float red[256];
    float ss = 0.f;
    for (int k = threadIdx.x; k < kE; k += 256) { float v = xr[k]; ss += v * v; }
    red[threadIdx.x] = ss; __syncthreads();
    for (int s = 128; s > 0; s >>= 1) {
        if (threadIdx.x < s) red[threadIdx.x] += red[threadIdx.x + s];
        __syncthreads();
    }
    float scale = rsqrtf(red[0] / (float)kE + 1e-6f);
    for (int k = threadIdx.x; k < kE; k += 256)
        g_h[(size_t)row * kE + k] = xr[k] * scale * w[k];
}

// ---------------- bf16 hi/lo split MMA building blocks ----------------------
#define MMA16816(d, a, b0_, b1_) \
    asm volatile("mma.sync.aligned.m16n8k16.row.col.f32.bf16.bf16.f32 " \
        "{%0,%1,%2,%3}, {%4,%5,%6,%7}, {%8,%9}, {%0,%1,%2,%3};" \
        : "+f"((d)[0]), "+f"((d)[1]), "+f"((d)[2]), "+f"((d)[3]) \
        : "r"((a)[0]), "r"((a)[1]), "r"((a)[2]), "r"((a)[3]), \
          "r"(b0_), "r"(b1_))

#define SMSTRIDE 24   // bf16 per smem row: 12 words -> conflict-free fragment loads

// ---------------- tensor-core C = A * B^T (hi/lo split, 3 MMAs) -------------
// Block 256 thr = 8 warps; C tile 128x128; warp tile 32x64 (warps 4(M) x 2(N)).
__global__ void __launch_bounds__(256, 2)
mma_abt(const float* __restrict__ A, int nacc, size_t accstride,
        const float* __restrict__ B0, const float* __restrict__ B1,
        float* C0, float* C1,
        int lda, int ldb, int ldc, int K,
        size_t az, size_t bz, size_t cz, int sym, int norm64)
{
    const int z = blockIdx.z;
    int bi, bj;
    if (sym) {
        int l = blockIdx.x;
        bi = (int)((sqrtf(8.f * l + 1.f) - 1.f) * 0.5f);
        while (bi * (bi + 1) / 2 > l) bi--;
        while ((bi + 1) * (bi + 2) / 2 <= l) bi++;
        bj = l - bi * (bi + 1) / 2;
    } else {
        bi = blockIdx.y; bj = blockIdx.x;
    }
    const float* Ap = A + az * (size_t)z;
    const float* Bp; float* Cp;
    if (B1) { Bp = z ? B1 : B0; Cp = z ? C1 : C0; }
    else    { Bp = B0 + bz * (size_t)z; Cp = C0 + cz * (size_t)z; }
    const int bm = bi * 128, bn = bj * 128;

    __shared__ __nv_bfloat16 Ah[128][SMSTRIDE], Al[128][SMSTRIDE];
    __shared__ __nv_bfloat16 Bh[128][SMSTRIDE], Bl[128][SMSTRIDE];

    const int tid  = threadIdx.x;
    const int lane = tid & 31;
    const int wid  = tid >> 5;
    const int g    = lane >> 2;
    const int t    = lane & 3;
    const int wm   = (wid & 3) * 32;
    const int wn   = (wid >> 2) * 64;
    const int sk   = tid & 15;
    const int sm0  = tid >> 4;

    float acc[2][8][4];
    #pragma unroll
    for (int mi = 0; mi < 2; mi++)
        #pragma unroll
        for (int ni = 0; ni < 8; ni++)
            #pragma unroll
            for (int c = 0; c < 4; c++) acc[mi][ni][c] = 0.f;

    float ra[8], rb[8];
    #pragma unroll
    for (int i = 0; i < 8; i++) {
        int m = sm0 + i * 16;
        size_t ai = (size_t)(bm + m) * lda + sk;
        float av = Ap[ai];
        for (int c = 1; c < nacc; c++) av += Ap[ai + accstride * c];
        ra[i] = av;
        rb[i] = Bp[(size_t)(bn + m) * ldb + sk];
    }

    for (int k0 = 0; k0 < K; k0 += 16) {
        #pragma unroll
        for (int i = 0; i < 8; i++) {
            int m = sm0 + i * 16;
            __nv_bfloat16 h = __float2bfloat16_rn(ra[i]);
            Ah[m][sk] = h;
            Al[m][sk] = __float2bfloat16_rn(ra[i] - __bfloat162float(h));
            h = __float2bfloat16_rn(rb[i]);
            Bh[m][sk] = h;
            Bl[m][sk] = __float2bfloat16_rn(rb[i] - __bfloat162float(h));
        }
        __syncthreads();
        if (k0 + 16 < K) {
            #pragma unroll
            for (int i = 0; i < 8; i++) {
                int m = sm0 + i * 16;
                size_t ai = (size_t)(bm + m) * lda + (k0 + 16 + sk);
                float av = Ap[ai];
                for (int c = 1; c < nacc; c++) av += Ap[ai + accstride * c];
                ra[i] = av;
                rb[i] = Bp[(size_t)(bn + m) * ldb + (k0 + 16 + sk)];
            }
        }
        uint32_t Afh[2][4], Afl[2][4];
        #pragma unroll
        for (int mi = 0; mi < 2; mi++) {
            int r = wm + 16 * mi + g;
            Afh[mi][0] = *(const uint32_t*)&Ah[r][2 * t];
            Afh[mi][1] = *(const uint32_t*)&Ah[r + 8][2 * t];
            Afh[mi][2] = *(const uint32_t*)&Ah[r][2 * t + 8];
            Afh[mi][3] = *(const uint32_t*)&Ah[r + 8][2 * t + 8];
            Afl[mi][0] = *(const uint32_t*)&Al[r][2 * t];
            Afl[mi][1] = *(const uint32_t*)&Al[r + 8][2 * t];
            Afl[mi][2] = *(const uint32_t*)&Al[r][2 * t + 8];
            Afl[mi][3] = *(const uint32_t*)&Al[r + 8][2 * t + 8];
        }
        #pragma unroll
        for (int ni = 0; ni < 8; ni++) {
            int n = wn + 8 * ni + g;
            uint32_t bh0 = *(const uint32_t*)&Bh[n][2 * t];
            uint32_t bh1 = *(const uint32_t*)&Bh[n][2 * t + 8];
            uint32_t bl0 = *(const uint32_t*)&Bl[n][2 * t];
            uint32_t bl1 = *(const uint32_t*)&Bl[n][2 * t + 8];
            #pragma unroll
            for (int mi = 0; mi < 2; mi++) {
                MMA16816(acc[mi][ni], Afh[mi], bh0, bh1);
                MMA16816(acc[mi][ni], Afh[mi], bl0, bl1);
                MMA16816(acc[mi][ni], Afl[mi], bh0, bh1);
            }
        }
        __syncthreads();
    }

    if (norm64 && B1 && z == 0) {
        #pragma unroll
        for (int mi = 0; mi < 2; mi++) {
            float s0 = 0.f, s1 = 0.f;
            #pragma unroll
            for (int ni = 0; ni < 8; ni++) {
                s0 += acc[mi][ni][0] * acc[mi][ni][0] + acc[mi][ni][1] * acc[mi][ni][1];
                s1 += acc[mi][ni][2] * acc[mi][ni][2] + acc[mi][ni][3] * acc[mi][ni][3];
            }
            s0 += __shfl_xor_sync(0xffffffffu, s0, 1);
            s0 += __shfl_xor_sync(0xffffffffu, s0, 2);
            s1 += __shfl_xor_sync(0xffffffffu, s1, 1);
            s1 += __shfl_xor_sync(0xffffffffu, s1, 2);
            float inv0 = rsqrtf(fmaxf(s0, 1e-24f));
            float inv1 = rsqrtf(fmaxf(s1, 1e-24f));
            #pragma unroll
            for (int ni = 0; ni < 8; ni++) {
                acc[mi][ni][0] *= inv0; acc[mi][ni][1] *= inv0;
                acc[mi][ni][2] *= inv1; acc[mi][ni][3] *= inv1;
            }
        }
    }

    #pragma unroll
    for (int mi = 0; mi < 2; mi++)
        #pragma unroll
        for (int ni = 0; ni < 8; ni++) {
            int r = bm + wm + 16 * mi + g;
            int c = bn + wn + 8 * ni + 2 * t;
            *(float2*)&Cp[(size_t)r * ldc + c]       = make_float2(acc[mi][ni][0], acc[mi][ni][1]);
            *(float2*)&Cp[(size_t)(r + 8) * ldc + c] = make_float2(acc[mi][ni][2], acc[mi][ni][3]);
        }
    if (sym && bj < bi) {
        #pragma unroll
        for (int mi = 0; mi < 2; mi++)
            #pragma unroll
            for (int ni = 0; ni < 8; ni++) {
                int r = bm + wm + 16 * mi + g;
                int c = bn + wn + 8 * ni + 2 * t;
                Cp[(size_t)c * ldc + r]           = acc[mi][ni][0];
                Cp[(size_t)(c + 1) * ldc + r]     = acc[mi][ni][1];
                Cp[(size_t)c * ldc + r + 8]       = acc[mi][ni][2];
                Cp[(size_t)(c + 1) * ldc + r + 8] = acc[mi][ni][3];
            }
    }
}

// ---------------- fused score-transform + softmax (row-wise, float4 I/O) ----
__global__ void __launch_bounds__(512)
softmax_kernel(const float* __restrict__ emo, float* __restrict__ S)
{
    const int row = blockIdx.x;
    const int hd  = blockIdx.y;
    float* rp = S + ((size_t)hd * kT + row) * kT;
    float4* rp4 = (float4*)rp;
    __shared__ float kt[kT];
    __shared__ float wred[16];
    const int tid  = threadIdx.x;
    const int lane = tid & 31;
    const int wrp  = tid >> 5;
    for (int j = tid; j < kT; j += 512) kt[j] = g_ktab[j];
    const float c0 = g_c[0];
    const float gNone = g_c[1], gStr = g_c[2], gLoc = g_c[3], gBoth = g_c[4];
    const float mean = g_c[5], esc = g_c[6];
    const float ei = emo[row];
    __syncthreads();

    float4 sv = rp4[tid];
    float o[4] = {sv.x, sv.y, sv.z, sv.w};
    float m = -1e30f;
    #pragma unroll
    for (int u = 0; u < 4; u++) {
        int j = tid * 4 + u;
        float sim = fminf(fmaxf(o[u], -1.f), 1.f);
        float sc = -fmaxf(2.f - 2.f * sim, 0.f) * c0;
        sc = fminf(fmaxf(sc, -12.f), 12.f);
        int d = row > j ? row - j : j - row;
        float g;
        if (d <= kWIN) g = ((j & 7) == 0) ? gBoth : gLoc;
        else           g = ((j & 7) == 0) ? gStr  : gNone;
        sc += g;
        sc += (ei * kt[d] - mean) * esc;
        o[u] = sc;
        m = fmaxf(m, sc);
    }
    #pragma unroll
    for (int s = 16; s > 0; s >>= 1) m = fmaxf(m, __shfl_xor_sync(0xffffffffu, m, s));
    if (lane == 0) wred[wrp] = m;
    __syncthreads();
    {
        float tt = (lane < 16) ? wred[lane] : -1e30f;
        #pragma unroll
        for (int s = 8; s > 0; s >>= 1) tt = fmaxf(tt, __shfl_xor_sync(0xffffffffu, tt, s));
        if (tid == 0) wred[0] = tt;
    }
    __syncthreads();
    m = wred[0];

    float sum = 0.f;
    #pragma unroll
    for (int u = 0; u < 4; u++) { o[u] = __expf(o[u] - m); sum += o[u]; }
    __syncthreads();
    #pragma unroll
    for (int s = 16; s > 0; s >>= 1) sum += __shfl_xor_sync(0xffffffffu, sum, s);
    if (lane == 0) wred[wrp] = sum;
    __syncthreads();
    {
        float tt = (lane < 16) ? wred[lane] : 0.f;
        #pragma unroll
        for (int s = 8; s > 0; s >>= 1) tt += __shfl_xor_sync(0xffffffffu, tt, s);
        if (tid == 0) wred[0] = tt;
    }
    __syncthreads();
    float inv = 1.f / wred[0];
    rp4[tid] = make_float4(o[0] * inv, o[1] * inv, o[2] * inv, o[3] * inv);
}

// ---------------- PV on tensor cores: pvpart[chunk] = attn[:,kc] @ v[kc] ----
// C tile 128(M) x 64(N)=one head; 8 warps as 4(M) x 2(N), warp tile 32x32.
// A = attn (row-major, lda=kT). B = v[k][hd*64+n]: transposed during staging
// into Bs[n][k]. Same hi/lo split (attn and v both).
__global__ void __launch_bounds__(256, 2)
pv_mma(const float* __restrict__ S)
{
    const int hd    = blockIdx.z;
    const int chunk = blockIdx.y;
    const int bm    = blockIdx.x * 128;
    const float* A = S + (size_t)hd * kT * kT;
    const float* B = g_v + hd * kD;          // B[k][n] at B[k*kE + n], n<64

    __shared__ __nv_bfloat16 Ah[128][SMSTRIDE], Al[128][SMSTRIDE];
    __shared__ __nv_bfloat16 Bh[64][SMSTRIDE],  Bl[64][SMSTRIDE];

    const int tid  = threadIdx.x;
    const int lane = tid & 31;
    const int wid  = tid >> 5;
    const int g    = lane >> 2;
    const int t    = lane & 3;
    const int wm   = (wid & 3) * 32;
    const int wn   = (wid >> 2) * 32;        // 2 N-warps cover 64
    const int sk   = tid & 15;
    const int sm0  = tid >> 4;
    const int vn   = tid & 63;               // B staging: n
    const int vk0  = tid >> 6;               // B staging: k base (stride 4)

    float acc[2][4][4];
    #pragma unroll
    for (int mi = 0; mi < 2; mi++)
        #pragma unroll
        for (int ni = 0; ni < 4; ni++)
            #pragma unroll
            for (int c = 0; c < 4; c++) acc[mi][ni][c] = 0.f;

    const int kb = chunk * (kT / kPVSPLIT);
    const int ke2 = kb + (kT / kPVSPLIT);

    float ra[8], rb[4];
    #pragma unroll
    for (int i = 0; i < 8; i++)
        ra[i] = A[(size_t)(bm + sm0 + i * 16) * kT + (kb + sk)];
    #pragma unroll
    for (int i = 0; i < 4; i++)
        rb[i] = B[(size_t)(kb + vk0 + i * 4) * kE + vn];

    for (int k0 = kb; k0 < ke2; k0 += 16) {
        #pragma unroll
        for (int i = 0; i < 8; i++) {
            int m = sm0 + i * 16;
            __nv_bfloat16 h = __float2bfloat16_rn(ra[i]);
            Ah[m][sk] = h;
            Al[m][sk] = __float2bfloat16_rn(ra[i] - __bfloat162float(h));
        }
        #pragma unroll
        for (int i = 0; i < 4; i++) {
            int kk = vk0 + i * 4;            // 0..15
            __nv_bfloat16 h = __float2bfloat16_rn(rb[i]);
            Bh[vn][kk] = h;
            Bl[vn][kk] = __float2bfloat16_rn(rb[i] - __bfloat162float(h));
        }
        __syncthreads();
        if (k0 + 16 < ke2) {
            #pragma unroll
            for (int i = 0; i < 8; i++)
                ra[i] = A[(size_t)(bm + sm0 + i * 16) * kT + (k0 + 16 + sk)];
            #pragma unroll
            for (int i = 0; i < 4; i++)
                rb[i] = B[(size_t)(k0 + 16 + vk0 + i * 4) * kE + vn];
        }
        uint32_t Afh[2][4], Afl[2][4];
        #pragma unroll
        for (int mi = 0; mi < 2; mi++) {
            int r = wm + 16 * mi + g;
            Afh[mi][0] = *(const uint32_t*)&Ah[r][2 * t];
            Afh[mi][1] = *(const uint32_t*)&Ah[r + 8][2 * t];
            Afh[mi][2] = *(const uint32_t*)&Ah[r][2 * t + 8];
            Afh[mi][3] = *(const uint32_t*)&Ah[r + 8][2 * t + 8];
            Afl[mi][0] = *(const uint32_t*)&Al[r][2 * t];
            Afl[mi][1] = *(const uint32_t*)&Al[r + 8][2 * t];
            Afl[mi][2] = *(const uint32_t*)&Al[r][2 * t + 8];
            Afl[mi][3] = *(const uint32_t*)&Al[r + 8][2 * t + 8];
        }
        #pragma unroll
        for (int ni = 0; ni < 4; ni++) {
            int n = wn + 8 * ni + g;
            uint32_t bh0 = *(const uint32_t*)&Bh[n][2 * t];
            uint32_t bh1 = *(const uint32_t*)&Bh[n][2 * t + 8];
            uint32_t bl0 = *(const uint32_t*)&Bl[n][2 * t];
            uint32_t bl1 = *(const uint32_t*)&Bl[n][2 * t + 8];
            #pragma unroll
            for (int mi = 0; mi < 2; mi++) {
                MMA16816(acc[mi][ni], Afh[mi], bh0, bh1);
                MMA16816(acc[mi][ni], Afh[mi], bl0, bl1);
                MMA16816(acc[mi][ni], Afl[mi], bh0, bh1);
            }
        }
        __syncthreads();
    }

    float* Cp = g_pvpart + (size_t)chunk * kT * kE;
    #pragma unroll
    for (int mi = 0; mi < 2; mi++)
        #pragma unroll
        for (int ni = 0; ni < 4; ni++) {
            int r = bm + wm + 16 * mi + g;
            int c = hd * kD + wn + 8 * ni + 2 * t;
            *(float2*)&Cp[(size_t)r * kE + c]       = make_float2(acc[mi][ni][0], acc[mi][ni][1]);
            *(float2*)&Cp[(size_t)(r + 8) * kE + c] = make_float2(acc[mi][ni][2], acc[mi][ni][3]);
        }
}

// ---------------- host launcher ----------------
extern "C" void kernel_launch(void* const* d_in, const int* in_sizes, int n_in,
                              void* d_out, int out_size)
{
    const float* x    = (const float*)d_in[0];
    const float* emo  = (const float*)d_in[1];
    const float* wqk  = (const float*)d_in[2];
    const float* wv   = (const float*)d_in[3];
    const float* wout = (const float*)d_in[4];
    const float* rmsw = (const float*)d_in[5];
    const float* sig  = (const float*)d_in[6];
    const float* bl   = (const float*)d_in[7];
    const float* bg   = (const float*)d_in[8];

    float* outbuf = (float*)d_out;
    const long long OUTN = (long long)kT * kE;
    const long long ATTN = (long long)kH * kT * kT;
    const long long osz  = (long long)out_size;
    float* out_o = nullptr;
    float* attn  = nullptr;
    if (osz >= OUTN + ATTN)  { out_o = outbuf; attn = outbuf + OUTN; }
    else if (osz == ATTN)    { attn = outbuf; }
    else                     { out_o = outbuf; }

    void *ph, *pq, *pv_, *ppv, *pscr;
    cudaGetSymbolAddress(&ph,  g_h);
    cudaGetSymbolAddress(&pq,  g_q);
    cudaGetSymbolAddress(&pv_, g_v);
    cudaGetSymbolAddress(&ppv, g_pvpart);
    cudaGetSymbolAddress(&pscr, g_scratch);
    float* h_   = (float*)ph;
    float* q_   = (float*)pq;
    float* v_   = (float*)pv_;
    float* pvp  = (float*)ppv;
    float* S    = attn ? attn : (float*)pscr;

    consts_kernel<<<1, 1024>>>(emo, sig, bl, bg);
    rmsnorm_kernel<<<kT, 256>>>(x, rmsw);
    // shared = h @ w_qk^T (per-head L2 norm in epilogue) ; values = h @ w_v^T
    mma_abt<<<dim3(kE / 128, kT / 128, 2), 256>>>(h_, 1, 0, wqk, wv, q_, v_,
                                                  kE, kE, kE, kE, 0, 0, 0, 0, 1);
    // sim = q @ q^T per head (triangular grid, mirror store)
    mma_abt<<<dim3(kTRI, 1, kH), 256>>>(q_, 1, 0, q_, nullptr, S, nullptr,
                                        kE, kE, kT, kD,
                                        (size_t)kD, (size_t)kD,
                                        (size_t)kT * kT, 1, 0);
    softmax_kernel<<<dim3(kT, kH), 512>>>(emo, S);
    pv_mma<<<dim3(kT / 128, kPVSPLIT, kH), 256>>>(S);
    if (out_o)  // out = (sum of pv partials) @ w_out^T (recombine fused into A-load)
        mma_abt<<<dim3(kE / 128, kT / 128, 1), 256>>>(pvp, kPVSPLIT, (size_t)kT * kE,
                                                      wout, nullptr, out_o, nullptr,
                                                      kE, kE, kE, kE, 0, 0, 0, 0, 0);
}